// round 12
// baseline (speedup 1.0000x reference)
#include <cuda_runtime.h>
#include <cuda_bf16.h>
#include <cooperative_groups.h>
#include <math.h>

namespace cg = cooperative_groups;

#define C    24
#define HC   96
#define FT   48
#define NPOS (FT*FT)
#define P    16           // positions per block (144 blocks = 1 wave)
#define NBLK (NPOS / P)   // 144
#define XNORM_A 0.007843137718737125f
#define DELTA 1.8f
#define OUT_SCALE 0.02083333395421505f

// Dense hm_hp SIGMOIDS, channel-major [ch][pos] (only read for winner conf)
__device__ float g_hmhp[17 * NPOS];
// Per-block center argmax keys: (score_bits<<32) | (0xFFFFFFFF - pos)
__device__ unsigned long long g_part[NBLK];
// Per-block hps head at the block's local-best position [blk][34]
__device__ float g_kreg[NBLK * 34];
// Per-keypoint global argmax keys
__device__ unsigned long long g_ckey[17];

__device__ __forceinline__ float fast_sig(float v) {
    return __fdividef(1.0f, 1.0f + __expf(-v));
}

// ---------------------------------------------------------------------------
// Single cooperative kernel: 144 blocks x 256 threads.
// ---------------------------------------------------------------------------
__global__ __launch_bounds__(256) void fused_coop(
    const float* __restrict__ x,
    const float* __restrict__ w_dw0, const float* __restrict__ b_dw0,   // hm_hp
    const float* __restrict__ w1_0,  const float* __restrict__ b1_0,
    const float* __restrict__ w2_0,  const float* __restrict__ b2_0,
    const float* __restrict__ w_dw1, const float* __restrict__ b_dw1,   // hm
    const float* __restrict__ w1_1,  const float* __restrict__ b1_1,
    const float* __restrict__ w2_1,  const float* __restrict__ b2_1,
    const float* __restrict__ hps_dw_w, const float* __restrict__ hps_dw_b,
    const float* __restrict__ hps_w1,   const float* __restrict__ hps_b1,
    const float* __restrict__ hps_w2,   const float* __restrict__ hps_b2,
    const float* __restrict__ off_dw_w, const float* __restrict__ off_dw_b,
    const float* __restrict__ off_w1,   const float* __restrict__ off_b1,
    const float* __restrict__ off_w2,   const float* __restrict__ off_b2,
    float* __restrict__ out)
{
    cg::grid_group grid = cg::this_grid();

    __shared__ float xs[C][3][P + 2];
    __shared__ float ys[2][P][28];
    __shared__ float zs[2][P][100];
    __shared__ float ssig[17][P];         // this block's hm_hp sigmoids
    __shared__ unsigned long long skey[P];
    __shared__ int   s_ploc, s_ct;
    __shared__ float s_y[C];
    __shared__ float s_z[HC];
    __shared__ float s_kcy[17], s_kcx[17];

    const int tid   = threadIdx.x;
    const int lane  = tid & 31;
    const int wid   = tid >> 5;
    const int pbase = blockIdx.x * P;     // all 16 positions share one row
    const int row   = pbase / FT;
    const int col0  = pbase % FT;

    // reset global argmax keys (before sync 1; fenced by grid.sync)
    if (blockIdx.x == 0 && tid < 17) g_ckey[tid] = 0ULL;

    // ================= phase 1: heads =================
    for (int idx = tid; idx < C * 3 * (P + 2); idx += 256) {
        int c  = idx / (3 * (P + 2));
        int r  = (idx / (P + 2)) % 3;
        int cc = idx % (P + 2);
        int gi = row + r - 1;
        int gj = col0 + cc - 1;
        float v = 0.f;
        if (gi >= 0 && gi < FT && gj >= 0 && gj < FT)
            v = x[(c * FT + gi) * FT + gj] * XNORM_A - 1.0f;
        xs[c][r][cc] = v;
    }
    __syncthreads();

    for (int idx = tid; idx < 2 * C * P; idx += 256) {
        int h   = idx / (C * P);
        int rem = idx % (C * P);
        int c   = rem / P;
        int p   = rem % P;
        const float* wd = h ? w_dw1 : w_dw0;
        const float* bd = h ? b_dw1 : b_dw0;
        float acc = bd[c];
        #pragma unroll
        for (int r = 0; r < 3; r++)
            #pragma unroll
            for (int s = 0; s < 3; s++)
                acc += wd[c * 9 + r * 3 + s] * xs[c][r][p + s];
        ys[h][p][c] = acc;
    }
    __syncthreads();

    if (tid < 2 * HC) {
        int h  = tid / HC;
        int oc = tid % HC;
        const float* w1 = h ? w1_1 : w1_0;
        const float* b1 = h ? b1_1 : b1_0;
        float acc[P];
        float b = b1[oc];
        #pragma unroll
        for (int p = 0; p < P; p++) acc[p] = b;
        #pragma unroll
        for (int k = 0; k < C; k++) {
            float wv = __ldg(&w1[oc * C + k]);
            #pragma unroll
            for (int p = 0; p < P; p++) acc[p] += wv * ys[h][p][k];
        }
        #pragma unroll
        for (int p = 0; p < P; p++) zs[h][p][oc] = fmaxf(acc[p], 0.f);
    }
    __syncthreads();

    for (int idx = tid; idx < 18 * P; idx += 256) {
        int combo = idx / P;
        int p     = idx % P;
        int pos   = pbase + p;
        if (combo < 17) {
            int oc = combo;
            float acc = b2_0[oc];
            #pragma unroll 8
            for (int k = 0; k < HC; k++)
                acc += __ldg(&w2_0[oc * HC + k]) * zs[0][p][k];
            float sig = fast_sig(acc);
            ssig[oc][p] = sig;
            g_hmhp[oc * NPOS + pos] = sig;
        } else {
            float acc = b2_1[0];
            #pragma unroll 8
            for (int k = 0; k < HC; k++)
                acc += __ldg(&w2_1[k]) * zs[1][p][k];
            float sig = fast_sig(acc);
            float gy = (float)row - (FT * 0.5f);
            float gx = (float)(col0 + p) - (FT * 0.5f);
            float s = __fdividef(sig, sqrtf(gy * gy + gx * gx) + DELTA);
            skey[p] = ((unsigned long long)__float_as_uint(s) << 32)
                    | (unsigned long long)(0xFFFFFFFFu - (unsigned)pos);
        }
    }
    __syncthreads();

    if (tid == 0) {
        unsigned long long best = skey[0];
        #pragma unroll
        for (int p = 1; p < P; p++) if (skey[p] > best) best = skey[p];
        g_part[blockIdx.x] = best;
        s_ploc = (int)(0xFFFFFFFFu - (unsigned)(best & 0xFFFFFFFFu)) - pbase;
    }
    __syncthreads();

    // hps head at the block's local-best position (block-parallel)
    const int pl = s_ploc;
    if (tid < C) {
        float acc = hps_dw_b[tid];
        #pragma unroll
        for (int r = 0; r < 3; r++)
            #pragma unroll
            for (int s = 0; s < 3; s++)
                acc += __ldg(&hps_dw_w[tid * 9 + r * 3 + s]) * xs[tid][r][pl + s];
        s_y[tid] = acc;
    }
    __syncthreads();
    if (tid < HC) {
        float a = hps_b1[tid];
        #pragma unroll
        for (int kk = 0; kk < C; kk++) a += __ldg(&hps_w1[tid * C + kk]) * s_y[kk];
        s_z[tid] = fmaxf(a, 0.f);
    }
    __syncthreads();
    for (int ch = wid; ch < 34; ch += 8) {
        float a = __ldg(&hps_w2[ch * HC + lane])      * s_z[lane]
                + __ldg(&hps_w2[ch * HC + lane + 32]) * s_z[lane + 32]
                + __ldg(&hps_w2[ch * HC + lane + 64]) * s_z[lane + 64];
        #pragma unroll
        for (int off = 16; off; off >>= 1)
            a += __shfl_down_sync(0xffffffffu, a, off);
        if (lane == 0)
            g_kreg[blockIdx.x * 34 + ch] = a + hps_b2[ch];
    }

    // ================= grid barrier 1 =================
    grid.sync();

    // ================= phase 2: center + scores =================
    if (wid == 0) {
        unsigned long long key = 0ULL;
        for (int i = lane; i < NBLK; i += 32) {
            unsigned long long v = g_part[i];
            if (v > key) key = v;
        }
        #pragma unroll
        for (int off = 16; off; off >>= 1) {
            unsigned long long o = __shfl_down_sync(0xffffffffu, key, off);
            if (o > key) key = o;
        }
        if (lane == 0)
            s_ct = (int)(0xFFFFFFFFu - (unsigned)(key & 0xFFFFFFFFu));
    }
    __syncthreads();
    const int ct  = s_ct;
    const int cty = ct / FT, ctx = ct % FT;
    const int bsrc = ct / P;

    if (tid < 34) {
        float v = g_kreg[bsrc * 34 + tid] + ((tid & 1) ? (float)ctx : (float)cty);
        if (tid & 1) s_kcx[tid >> 1] = v;
        else         s_kcy[tid >> 1] = v;
    }
    __syncthreads();

    // score own 16 positions for all 17 keypoints; warp w: kpts w, w+8, w+16
    {
        const float rowf = (float)row;
        for (int k = wid; k < 17; k += 8) {
            unsigned long long key = 0ULL;
            if (lane < P) {
                float sig = ssig[k][lane];
                float dy = rowf - s_kcy[k];
                float dx = (float)(col0 + lane) - s_kcx[k];
                float s = __fdividef(sig, sqrtf(dy * dy + dx * dx) + DELTA);
                key = ((unsigned long long)__float_as_uint(s) << 32)
                    | (unsigned long long)(0xFFFFFFFFu - (unsigned)(pbase + lane));
            }
            #pragma unroll
            for (int off = 8; off; off >>= 1) {
                unsigned long long o = __shfl_down_sync(0xffffffffu, key, off);
                if (o > key) key = o;
            }
            if (lane == 0) atomicMax(&g_ckey[k], key);
        }
    }

    // ================= grid barrier 2 =================
    grid.sync();

    // ================= phase 3: decode tail (blocks 0..16) =================
    if (blockIdx.x >= 17) return;
    const int k = blockIdx.x;

    const unsigned long long fin = g_ckey[k];
    const int top = (int)(0xFFFFFFFFu - (unsigned)(fin & 0xFFFFFFFFu));
    const int ty  = top / FT, tx = top % FT;

    if (tid < C) {
        float acc = off_dw_b[tid];
        #pragma unroll
        for (int r = 0; r < 3; r++) {
            int gi = ty + r - 1;
            if (gi < 0 || gi >= FT) continue;
            #pragma unroll
            for (int s = 0; s < 3; s++) {
                int gj = tx + s - 1;
                if (gj < 0 || gj >= FT) continue;
                float xv = __ldg(&x[(tid * FT + gi) * FT + gj]) * XNORM_A - 1.0f;
                acc += __ldg(&off_dw_w[tid * 9 + r * 3 + s]) * xv;
            }
        }
        s_y[tid] = acc;
    }
    __syncthreads();
    if (tid < HC) {
        float a = off_b1[tid];
        #pragma unroll
        for (int kk = 0; kk < C; kk++) a += __ldg(&off_w1[tid * C + kk]) * s_y[kk];
        s_z[tid] = fmaxf(a, 0.f);
    }
    __syncthreads();
    if (wid < 2) {
        int oc = 2 * k + wid;
        float a = __ldg(&off_w2[oc * HC + lane])      * s_z[lane]
                + __ldg(&off_w2[oc * HC + lane + 32]) * s_z[lane + 32]
                + __ldg(&off_w2[oc * HC + lane + 64]) * s_z[lane + 64];
        #pragma unroll
        for (int off = 16; off; off >>= 1)
            a += __shfl_down_sync(0xffffffffu, a, off);
        if (lane == 0) {
            float base = wid ? (float)tx : (float)ty;
            out[k * 3 + wid] = (a + off_b2[oc] + base) * OUT_SCALE;
        }
    }
    if (tid == 64)
        out[k * 3 + 2] = g_hmhp[k * NPOS + top];
}

// ---------------------------------------------------------------------------
extern "C" void kernel_launch(void* const* d_in, const int* in_sizes, int n_in,
                              void* d_out, int out_size)
{
    const float* x    = (const float*)d_in[0];
    const float* a1   = (const float*)d_in[1];
    const float* a2   = (const float*)d_in[2];
    const float* a3   = (const float*)d_in[3];
    const float* a4   = (const float*)d_in[4];
    const float* a5   = (const float*)d_in[5];
    const float* a6   = (const float*)d_in[6];
    const float* a7   = (const float*)d_in[7];
    const float* a8   = (const float*)d_in[8];
    const float* a9   = (const float*)d_in[9];
    const float* a10  = (const float*)d_in[10];
    const float* a11  = (const float*)d_in[11];
    const float* a12  = (const float*)d_in[12];
    const float* a13  = (const float*)d_in[13];
    const float* a14  = (const float*)d_in[14];
    const float* a15  = (const float*)d_in[15];
    const float* a16  = (const float*)d_in[16];
    const float* a17  = (const float*)d_in[17];
    const float* a18  = (const float*)d_in[18];
    const float* a19  = (const float*)d_in[19];
    const float* a20  = (const float*)d_in[20];
    const float* a21  = (const float*)d_in[21];
    const float* a22  = (const float*)d_in[22];
    const float* a23  = (const float*)d_in[23];
    const float* a24  = (const float*)d_in[24];
    float* out = (float*)d_out;

    void* args[] = {
        (void*)&x,
        (void*)&a1,  (void*)&a2,  (void*)&a3,  (void*)&a4,
        (void*)&a5,  (void*)&a6,  (void*)&a7,  (void*)&a8,
        (void*)&a9,  (void*)&a10, (void*)&a11, (void*)&a12,
        (void*)&a13, (void*)&a14, (void*)&a15, (void*)&a16,
        (void*)&a17, (void*)&a18, (void*)&a19, (void*)&a20,
        (void*)&a21, (void*)&a22, (void*)&a23, (void*)&a24,
        (void*)&out
    };
    cudaLaunchCooperativeKernel((void*)fused_coop, dim3(NBLK), dim3(256),
                                args, 0, (cudaStream_t)0);
}

// round 13
// speedup vs baseline: 1.1389x; 1.1389x over previous
#include <cuda_runtime.h>
#include <cuda_bf16.h>
#include <math.h>

#define C    24
#define HC   96
#define FT   48
#define NPOS (FT*FT)
#define P    16           // positions per block (144 blocks = 1 wave)
#define NBLK (NPOS / P)   // 144
#define XNORM_A 0.007843137718737125f
#define DELTA 1.8f
#define OUT_SCALE 0.02083333395421505f

// Dense hm_hp SIGMOIDS, channel-major [ch][pos]
__device__ float g_hmhp[17 * NPOS];
// Per-block center argmax keys: (score_bits<<32) | (0xFFFFFFFF - pos)
__device__ unsigned long long g_part[NBLK];

__device__ __forceinline__ float fast_sig(float v) {
    return __fdividef(1.0f, 1.0f + __expf(-v));
}

// ---------------------------------------------------------------------------
// Kernel 1 (primary): dense hm_hp (sigmoid) + hm heads + per-block center key.
// 144 blocks x 256 threads. Triggers programmatic launch completion at end.
// ---------------------------------------------------------------------------
__global__ __launch_bounds__(256) void heads_kernel(
    const float* __restrict__ x,
    const float* __restrict__ w_dw0, const float* __restrict__ b_dw0,
    const float* __restrict__ w1_0,  const float* __restrict__ b1_0,
    const float* __restrict__ w2_0,  const float* __restrict__ b2_0,
    const float* __restrict__ w_dw1, const float* __restrict__ b_dw1,
    const float* __restrict__ w1_1,  const float* __restrict__ b1_1,
    const float* __restrict__ w2_1,  const float* __restrict__ b2_1)
{
    __shared__ float xs[C][3][P + 2];
    __shared__ float ys[2][P][28];
    __shared__ float zs[2][P][100];
    __shared__ unsigned long long skey[P];

    const int tid   = threadIdx.x;
    const int pbase = blockIdx.x * P;
    const int row   = pbase / FT;
    const int col0  = pbase % FT;

    for (int idx = tid; idx < C * 3 * (P + 2); idx += 256) {
        int c  = idx / (3 * (P + 2));
        int r  = (idx / (P + 2)) % 3;
        int cc = idx % (P + 2);
        int gi = row + r - 1;
        int gj = col0 + cc - 1;
        float v = 0.f;
        if (gi >= 0 && gi < FT && gj >= 0 && gj < FT)
            v = x[(c * FT + gi) * FT + gj] * XNORM_A - 1.0f;
        xs[c][r][cc] = v;
    }
    __syncthreads();

    for (int idx = tid; idx < 2 * C * P; idx += 256) {
        int h   = idx / (C * P);
        int rem = idx % (C * P);
        int c   = rem / P;
        int p   = rem % P;
        const float* wd = h ? w_dw1 : w_dw0;
        const float* bd = h ? b_dw1 : b_dw0;
        float acc = bd[c];
        #pragma unroll
        for (int r = 0; r < 3; r++)
            #pragma unroll
            for (int s = 0; s < 3; s++)
                acc += wd[c * 9 + r * 3 + s] * xs[c][r][p + s];
        ys[h][p][c] = acc;
    }
    __syncthreads();

    if (tid < 2 * HC) {
        int h  = tid / HC;
        int oc = tid % HC;
        const float* w1 = h ? w1_1 : w1_0;
        const float* b1 = h ? b1_1 : b1_0;
        float acc[P];
        float b = b1[oc];
        #pragma unroll
        for (int p = 0; p < P; p++) acc[p] = b;
        #pragma unroll
        for (int k = 0; k < C; k++) {
            float wv = __ldg(&w1[oc * C + k]);
            #pragma unroll
            for (int p = 0; p < P; p++) acc[p] += wv * ys[h][p][k];
        }
        #pragma unroll
        for (int p = 0; p < P; p++) zs[h][p][oc] = fmaxf(acc[p], 0.f);
    }
    __syncthreads();

    for (int idx = tid; idx < 18 * P; idx += 256) {
        int combo = idx / P;
        int p     = idx % P;
        int pos   = pbase + p;
        if (combo < 17) {
            int oc = combo;
            float acc = b2_0[oc];
            #pragma unroll 8
            for (int k = 0; k < HC; k++)
                acc += __ldg(&w2_0[oc * HC + k]) * zs[0][p][k];
            g_hmhp[oc * NPOS + pos] = fast_sig(acc);
        } else {
            float acc = b2_1[0];
            #pragma unroll 8
            for (int k = 0; k < HC; k++)
                acc += __ldg(&w2_1[k]) * zs[1][p][k];
            float sig = fast_sig(acc);
            float gy = (float)row - (FT * 0.5f);
            float gx = (float)(col0 + p) - (FT * 0.5f);
            float s = __fdividef(sig, sqrtf(gy * gy + gx * gx) + DELTA);
            skey[p] = ((unsigned long long)__float_as_uint(s) << 32)
                    | (unsigned long long)(0xFFFFFFFFu - (unsigned)pos);
        }
    }
    __syncthreads();
    if (tid == 0) {
        unsigned long long best = skey[0];
        #pragma unroll
        for (int p = 1; p < P; p++) if (skey[p] > best) best = skey[p];
        g_part[blockIdx.x] = best;
    }

    // allow the dependent decode kernel to launch
    cudaTriggerProgrammaticLaunchCompletion();
}

// ---------------------------------------------------------------------------
// Kernel 2 (dependent, PDL): decode, 17 blocks x 256 threads.
// Preamble (no dependency): stage all hps/off weights into smem.
// Then cudaGridDependencySynchronize() and the R9 decode phases.
// ---------------------------------------------------------------------------
__global__ __launch_bounds__(256) void decode_kernel(
    const float* __restrict__ x,
    const float* __restrict__ hps_dw_w, const float* __restrict__ hps_dw_b,
    const float* __restrict__ hps_w1,   const float* __restrict__ hps_b1,
    const float* __restrict__ hps_w2,   const float* __restrict__ hps_b2,
    const float* __restrict__ off_dw_w, const float* __restrict__ off_dw_b,
    const float* __restrict__ off_w1,   const float* __restrict__ off_b1,
    const float* __restrict__ off_w2,   const float* __restrict__ off_b2,
    float* __restrict__ out)
{
    __shared__ float s_hw1[HC * C];      // 9216 B
    __shared__ float s_ow1[HC * C];      // 9216 B
    __shared__ float s_hdw[C * 9], s_odw[C * 9];
    __shared__ float s_hdb[C],     s_odb[C];
    __shared__ float s_hb1[HC],    s_ob1[HC];
    __shared__ float s_hw2[2 * HC], s_ow2[2 * HC];   // rows 2k, 2k+1
    __shared__ float s_hb2[2],      s_ob2[2];
    __shared__ unsigned long long s_k[8];
    __shared__ int   s_ct, s_top;
    __shared__ float s_y[C];
    __shared__ float s_z[HC];
    __shared__ float s_kc[2];

    const int k    = blockIdx.x;
    const int tid  = threadIdx.x;
    const int lane = tid & 31;
    const int wid  = tid >> 5;

    // ---- preamble: weight staging, independent of the primary kernel
    for (int i = tid; i < HC * C; i += 256) {
        s_hw1[i] = __ldg(&hps_w1[i]);
        s_ow1[i] = __ldg(&off_w1[i]);
    }
    for (int i = tid; i < C * 9; i += 256) {
        s_hdw[i] = __ldg(&hps_dw_w[i]);
        s_odw[i] = __ldg(&off_dw_w[i]);
    }
    if (tid < C)  { s_hdb[tid] = __ldg(&hps_dw_b[tid]); s_odb[tid] = __ldg(&off_dw_b[tid]); }
    if (tid < HC) { s_hb1[tid] = __ldg(&hps_b1[tid]);   s_ob1[tid] = __ldg(&off_b1[tid]); }
    for (int i = tid; i < 2 * HC; i += 256) {
        s_hw2[i] = __ldg(&hps_w2[2 * k * HC + i]);
        s_ow2[i] = __ldg(&off_w2[2 * k * HC + i]);
    }
    if (tid < 2) { s_hb2[tid] = __ldg(&hps_b2[2 * k + tid]); s_ob2[tid] = __ldg(&off_b2[2 * k + tid]); }

    // ---- wait for the primary grid's results
    cudaGridDependencySynchronize();
    __syncthreads();

    // ---- A: reduce 144 per-block center keys (warp 0)
    if (wid == 0) {
        unsigned long long key = 0ULL;
        for (int i = lane; i < NBLK; i += 32) {
            unsigned long long v = g_part[i];
            if (v > key) key = v;
        }
        #pragma unroll
        for (int off = 16; off; off >>= 1) {
            unsigned long long o = __shfl_down_sync(0xffffffffu, key, off);
            if (o > key) key = o;
        }
        if (lane == 0)
            s_ct = (int)(0xFFFFFFFFu - (unsigned)(key & 0xFFFFFFFFu));
    }
    __syncthreads();
    const int ct  = s_ct;
    const int cty = ct / FT, ctx = ct % FT;

    // ---- B: hps head at the center (weights from smem)
    if (tid < C) {
        float acc = s_hdb[tid];
        #pragma unroll
        for (int r = 0; r < 3; r++) {
            int gi = cty + r - 1;
            if (gi < 0 || gi >= FT) continue;
            #pragma unroll
            for (int s = 0; s < 3; s++) {
                int gj = ctx + s - 1;
                if (gj < 0 || gj >= FT) continue;
                float xv = __ldg(&x[(tid * FT + gi) * FT + gj]) * XNORM_A - 1.0f;
                acc += s_hdw[tid * 9 + r * 3 + s] * xv;
            }
        }
        s_y[tid] = acc;
    }
    __syncthreads();
    if (tid < HC) {
        float a = s_hb1[tid];
        #pragma unroll
        for (int kk = 0; kk < C; kk++) a += s_hw1[tid * C + kk] * s_y[kk];
        s_z[tid] = fmaxf(a, 0.f);
    }
    __syncthreads();
    if (wid < 2) {
        float a = s_hw2[wid * HC + lane]      * s_z[lane]
                + s_hw2[wid * HC + lane + 32] * s_z[lane + 32]
                + s_hw2[wid * HC + lane + 64] * s_z[lane + 64];
        #pragma unroll
        for (int off = 16; off; off >>= 1)
            a += __shfl_down_sync(0xffffffffu, a, off);
        if (lane == 0)
            s_kc[wid] = a + s_hb2[wid] + (wid ? (float)ctx : (float)cty);
    }
    __syncthreads();

    // ---- C: distance-weighted argmax (u64 keys, 9 positions/thread)
    const float ky = s_kc[0];
    const float kx = s_kc[1];
    const float* hmap = g_hmhp + k * NPOS;
    {
        unsigned long long best = 0ULL;
        #pragma unroll
        for (int i = 0; i < NPOS / 256; i++) {
            int p = tid + i * 256;
            float sig = __ldg(&hmap[p]);
            int py = p / FT;
            float dy = (float)py - ky;
            float dx = (float)(p - py * FT) - kx;
            float s = __fdividef(sig, sqrtf(dy * dy + dx * dx) + DELTA);
            unsigned long long key =
                ((unsigned long long)__float_as_uint(s) << 32)
                | (unsigned long long)(0xFFFFFFFFu - (unsigned)p);
            if (key > best) best = key;
        }
        #pragma unroll
        for (int off = 16; off; off >>= 1) {
            unsigned long long o = __shfl_down_sync(0xffffffffu, best, off);
            if (o > best) best = o;
        }
        if (lane == 0) s_k[wid] = best;
        __syncthreads();
        if (tid == 0) {
            unsigned long long b = s_k[0];
            #pragma unroll
            for (int w = 1; w < 8; w++) if (s_k[w] > b) b = s_k[w];
            s_top = (int)(0xFFFFFFFFu - (unsigned)(b & 0xFFFFFFFFu));
        }
        __syncthreads();
    }
    const int top = s_top;
    const int ty  = top / FT, tx = top % FT;

    // ---- D: hp_offset head at the winner (weights from smem)
    if (tid < C) {
        float acc = s_odb[tid];
        #pragma unroll
        for (int r = 0; r < 3; r++) {
            int gi = ty + r - 1;
            if (gi < 0 || gi >= FT) continue;
            #pragma unroll
            for (int s = 0; s < 3; s++) {
                int gj = tx + s - 1;
                if (gj < 0 || gj >= FT) continue;
                float xv = __ldg(&x[(tid * FT + gi) * FT + gj]) * XNORM_A - 1.0f;
                acc += s_odw[tid * 9 + r * 3 + s] * xv;
            }
        }
        s_y[tid] = acc;
    }
    __syncthreads();
    if (tid < HC) {
        float a = s_ob1[tid];
        #pragma unroll
        for (int kk = 0; kk < C; kk++) a += s_ow1[tid * C + kk] * s_y[kk];
        s_z[tid] = fmaxf(a, 0.f);
    }
    __syncthreads();
    if (wid < 2) {
        float a = s_ow2[wid * HC + lane]      * s_z[lane]
                + s_ow2[wid * HC + lane + 32] * s_z[lane + 32]
                + s_ow2[wid * HC + lane + 64] * s_z[lane + 64];
        #pragma unroll
        for (int off = 16; off; off >>= 1)
            a += __shfl_down_sync(0xffffffffu, a, off);
        if (lane == 0) {
            float base = wid ? (float)tx : (float)ty;
            out[k * 3 + wid] = (a + s_ob2[wid] + base) * OUT_SCALE;
        }
    }
    if (tid == 64)
        out[k * 3 + 2] = hmap[top];   // stored sigmoid
}

// ---------------------------------------------------------------------------
extern "C" void kernel_launch(void* const* d_in, const int* in_sizes, int n_in,
                              void* d_out, int out_size)
{
    const float* x = (const float*)d_in[0];

    heads_kernel<<<NBLK, 256>>>(
        x,
        (const float*)d_in[1],  (const float*)d_in[2],
        (const float*)d_in[3],  (const float*)d_in[4],
        (const float*)d_in[5],  (const float*)d_in[6],
        (const float*)d_in[7],  (const float*)d_in[8],
        (const float*)d_in[9],  (const float*)d_in[10],
        (const float*)d_in[11], (const float*)d_in[12]);

    // dependent launch: overlap decode's setup + weight staging with heads
    cudaLaunchConfig_t cfg = {};
    cfg.gridDim  = dim3(17);
    cfg.blockDim = dim3(256);
    cfg.dynamicSmemBytes = 0;
    cfg.stream = (cudaStream_t)0;
    cudaLaunchAttribute attr[1];
    attr[0].id = cudaLaunchAttributeProgrammaticStreamSerialization;
    attr[0].val.programmaticStreamSerializationAllowed = 1;
    cfg.attrs = attr;
    cfg.numAttrs = 1;

    cudaLaunchKernelEx(&cfg, decode_kernel,
        x,
        (const float*)d_in[13], (const float*)d_in[14],
        (const float*)d_in[15], (const float*)d_in[16],
        (const float*)d_in[17], (const float*)d_in[18],
        (const float*)d_in[19], (const float*)d_in[20],
        (const float*)d_in[21], (const float*)d_in[22],
        (const float*)d_in[23], (const float*)d_in[24],
        (float*)d_out);
}

// round 14
// speedup vs baseline: 1.2390x; 1.0879x over previous
#include <cuda_runtime.h>
#include <cuda_bf16.h>
#include <math.h>

#define C    24
#define HC   96
#define FT   48
#define NPOS (FT*FT)
#define P    16           // positions per block (144 blocks = 1 wave)
#define NBLK (NPOS / P)   // 144
#define HT   384          // heads kernel block size
#define XNORM_A 0.007843137718737125f
#define DELTA 1.8f
#define OUT_SCALE 0.02083333395421505f

// Dense hm_hp SIGMOIDS, channel-major [ch][pos]
__device__ float g_hmhp[17 * NPOS];
// Per-block center argmax keys: (score_bits<<32) | (0xFFFFFFFF - pos)
__device__ unsigned long long g_part[NBLK];

__device__ __forceinline__ float fast_sig(float v) {
    return __fdividef(1.0f, 1.0f + __expf(-v));
}

// ---------------------------------------------------------------------------
// Kernel 1 (primary): dense hm_hp (sigmoid) + hm heads + per-block center key.
// 144 blocks x 384 threads. pw1 split into two 8-position halves per row.
// ---------------------------------------------------------------------------
__global__ __launch_bounds__(HT) void heads_kernel(
    const float* __restrict__ x,
    const float* __restrict__ w_dw0, const float* __restrict__ b_dw0,
    const float* __restrict__ w1_0,  const float* __restrict__ b1_0,
    const float* __restrict__ w2_0,  const float* __restrict__ b2_0,
    const float* __restrict__ w_dw1, const float* __restrict__ b_dw1,
    const float* __restrict__ w1_1,  const float* __restrict__ b1_1,
    const float* __restrict__ w2_1,  const float* __restrict__ b2_1)
{
    __shared__ float xs[C][3][P + 2];
    __shared__ float ys[2][P][28];
    __shared__ float zs[2][P][100];
    __shared__ unsigned long long skey[P];

    const int tid   = threadIdx.x;
    const int pbase = blockIdx.x * P;
    const int row   = pbase / FT;
    const int col0  = pbase % FT;

    // ---- stage X: normalized 3x(P+2) neighborhood, all 24 channels
    for (int idx = tid; idx < C * 3 * (P + 2); idx += HT) {
        int c  = idx / (3 * (P + 2));
        int r  = (idx / (P + 2)) % 3;
        int cc = idx % (P + 2);
        int gi = row + r - 1;
        int gj = col0 + cc - 1;
        float v = 0.f;
        if (gi >= 0 && gi < FT && gj >= 0 && gj < FT)
            v = x[(c * FT + gi) * FT + gj] * XNORM_A - 1.0f;
        xs[c][r][cc] = v;
    }
    __syncthreads();

    // ---- stage Y: depthwise 3x3, 2 heads: 768 tasks, 2 per thread
    for (int idx = tid; idx < 2 * C * P; idx += HT) {
        int h   = idx / (C * P);
        int rem = idx % (C * P);
        int c   = rem / P;
        int p   = rem % P;
        const float* wd = h ? w_dw1 : w_dw0;
        const float* bd = h ? b_dw1 : b_dw0;
        float acc = bd[c];
        #pragma unroll
        for (int r = 0; r < 3; r++)
            #pragma unroll
            for (int s = 0; s < 3; s++)
                acc += wd[c * 9 + r * 3 + s] * xs[c][r][p + s];
        ys[h][p][c] = acc;
    }
    __syncthreads();

    // ---- stage Z: pw1 (24->96) + relu, split into two 8-position halves:
    //      2 heads x 96 oc x 2 halves = 384 tasks, exactly 1 per thread.
    {
        int h    = tid / (HC * 2);            // 0..1
        int rem  = tid % (HC * 2);
        int oc   = rem >> 1;                  // 0..95
        int half = rem & 1;                   // 0..1
        int p0   = half * 8;
        const float* w1 = h ? w1_1 : w1_0;
        const float* b1 = h ? b1_1 : b1_0;
        float acc[8];
        float b = b1[oc];
        #pragma unroll
        for (int p = 0; p < 8; p++) acc[p] = b;
        #pragma unroll
        for (int k = 0; k < C; k++) {
            float wv = __ldg(&w1[oc * C + k]);
            #pragma unroll
            for (int p = 0; p < 8; p++) acc[p] += wv * ys[h][p0 + p][k];
        }
        #pragma unroll
        for (int p = 0; p < 8; p++) zs[h][p0 + p][oc] = fmaxf(acc[p], 0.f);
    }
    __syncthreads();

    // ---- stage O: pw2. 18 combos x 16 positions = 288 tasks (tid < 288)
    if (tid < 18 * P) {
        int combo = tid / P;
        int p     = tid % P;
        int pos   = pbase + p;
        if (combo < 17) {
            int oc = combo;
            float acc = b2_0[oc];
            #pragma unroll 8
            for (int k = 0; k < HC; k++)
                acc += __ldg(&w2_0[oc * HC + k]) * zs[0][p][k];
            g_hmhp[oc * NPOS + pos] = fast_sig(acc);
        } else {
            float acc = b2_1[0];
            #pragma unroll 8
            for (int k = 0; k < HC; k++)
                acc += __ldg(&w2_1[k]) * zs[1][p][k];
            float sig = fast_sig(acc);
            float gy = (float)row - (FT * 0.5f);
            float gx = (float)(col0 + p) - (FT * 0.5f);
            float s = __fdividef(sig, sqrtf(gy * gy + gx * gx) + DELTA);
            skey[p] = ((unsigned long long)__float_as_uint(s) << 32)
                    | (unsigned long long)(0xFFFFFFFFu - (unsigned)pos);
        }
    }
    __syncthreads();
    if (tid == 0) {
        unsigned long long best = skey[0];
        #pragma unroll
        for (int p = 1; p < P; p++) if (skey[p] > best) best = skey[p];
        g_part[blockIdx.x] = best;
    }

    cudaTriggerProgrammaticLaunchCompletion();
}

// ---------------------------------------------------------------------------
// Kernel 2 (dependent, PDL): decode, 17 blocks x 256 threads.
// Preamble: stage all hps/off weights into smem (independent of primary).
// Post-sync: prefetch hmap into registers, then A -> B -> C -> D.
// ---------------------------------------------------------------------------
__global__ __launch_bounds__(256) void decode_kernel(
    const float* __restrict__ x,
    const float* __restrict__ hps_dw_w, const float* __restrict__ hps_dw_b,
    const float* __restrict__ hps_w1,   const float* __restrict__ hps_b1,
    const float* __restrict__ hps_w2,   const float* __restrict__ hps_b2,
    const float* __restrict__ off_dw_w, const float* __restrict__ off_dw_b,
    const float* __restrict__ off_w1,   const float* __restrict__ off_b1,
    const float* __restrict__ off_w2,   const float* __restrict__ off_b2,
    float* __restrict__ out)
{
    __shared__ float s_hw1[HC * C];      // 9216 B
    __shared__ float s_ow1[HC * C];      // 9216 B
    __shared__ float s_hdw[C * 9], s_odw[C * 9];
    __shared__ float s_hdb[C],     s_odb[C];
    __shared__ float s_hb1[HC],    s_ob1[HC];
    __shared__ float s_hw2[2 * HC], s_ow2[2 * HC];
    __shared__ float s_hb2[2],      s_ob2[2];
    __shared__ unsigned long long s_k[8];
    __shared__ int   s_ct, s_top;
    __shared__ float s_y[C];
    __shared__ float s_z[HC];
    __shared__ float s_kc[2];

    const int k    = blockIdx.x;
    const int tid  = threadIdx.x;
    const int lane = tid & 31;
    const int wid  = tid >> 5;

    // ---- preamble: weight staging, independent of the primary kernel
    for (int i = tid; i < HC * C; i += 256) {
        s_hw1[i] = __ldg(&hps_w1[i]);
        s_ow1[i] = __ldg(&off_w1[i]);
    }
    for (int i = tid; i < C * 9; i += 256) {
        s_hdw[i] = __ldg(&hps_dw_w[i]);
        s_odw[i] = __ldg(&off_dw_w[i]);
    }
    if (tid < C)  { s_hdb[tid] = __ldg(&hps_dw_b[tid]); s_odb[tid] = __ldg(&off_dw_b[tid]); }
    if (tid < HC) { s_hb1[tid] = __ldg(&hps_b1[tid]);   s_ob1[tid] = __ldg(&off_b1[tid]); }
    for (int i = tid; i < 2 * HC; i += 256) {
        s_hw2[i] = __ldg(&hps_w2[2 * k * HC + i]);
        s_ow2[i] = __ldg(&off_w2[2 * k * HC + i]);
    }
    if (tid < 2) { s_hb2[tid] = __ldg(&hps_b2[2 * k + tid]); s_ob2[tid] = __ldg(&off_b2[2 * k + tid]); }

    // ---- wait for the primary grid's results
    cudaGridDependencySynchronize();

    // ---- prefetch this keypoint's heatmap slice into registers NOW;
    //      the L2 latency overlaps phases A and B below.
    const float* hmap = g_hmhp + k * NPOS;
    float pre[NPOS / 256];
    #pragma unroll
    for (int i = 0; i < NPOS / 256; i++)
        pre[i] = __ldg(&hmap[tid + i * 256]);

    // ---- A: reduce 144 per-block center keys (warp 0)
    if (wid == 0) {
        unsigned long long key = 0ULL;
        for (int i = lane; i < NBLK; i += 32) {
            unsigned long long v = g_part[i];
            if (v > key) key = v;
        }
        #pragma unroll
        for (int off = 16; off; off >>= 1) {
            unsigned long long o = __shfl_down_sync(0xffffffffu, key, off);
            if (o > key) key = o;
        }
        if (lane == 0)
            s_ct = (int)(0xFFFFFFFFu - (unsigned)(key & 0xFFFFFFFFu));
    }
    __syncthreads();   // also orders the preamble smem staging
    const int ct  = s_ct;
    const int cty = ct / FT, ctx = ct % FT;

    // ---- B: hps head at the center (weights from smem)
    if (tid < C) {
        float acc = s_hdb[tid];
        #pragma unroll
        for (int r = 0; r < 3; r++) {
            int gi = cty + r - 1;
            if (gi < 0 || gi >= FT) continue;
            #pragma unroll
            for (int s = 0; s < 3; s++) {
                int gj = ctx + s - 1;
                if (gj < 0 || gj >= FT) continue;
                float xv = __ldg(&x[(tid * FT + gi) * FT + gj]) * XNORM_A - 1.0f;
                acc += s_hdw[tid * 9 + r * 3 + s] * xv;
            }
        }
        s_y[tid] = acc;
    }
    __syncthreads();
    if (tid < HC) {
        float a = s_hb1[tid];
        #pragma unroll
        for (int kk = 0; kk < C; kk++) a += s_hw1[tid * C + kk] * s_y[kk];
        s_z[tid] = fmaxf(a, 0.f);
    }
    __syncthreads();
    if (wid < 2) {
        float a = s_hw2[wid * HC + lane]      * s_z[lane]
                + s_hw2[wid * HC + lane + 32] * s_z[lane + 32]
                + s_hw2[wid * HC + lane + 64] * s_z[lane + 64];
        #pragma unroll
        for (int off = 16; off; off >>= 1)
            a += __shfl_down_sync(0xffffffffu, a, off);
        if (lane == 0)
            s_kc[wid] = a + s_hb2[wid] + (wid ? (float)ctx : (float)cty);
    }
    __syncthreads();

    // ---- C: distance-weighted argmax using prefetched registers
    const float ky = s_kc[0];
    const float kx = s_kc[1];
    {
        unsigned long long best = 0ULL;
        #pragma unroll
        for (int i = 0; i < NPOS / 256; i++) {
            int p = tid + i * 256;
            int py = p / FT;
            float dy = (float)py - ky;
            float dx = (float)(p - py * FT) - kx;
            float s = __fdividef(pre[i], sqrtf(dy * dy + dx * dx) + DELTA);
            unsigned long long key =
                ((unsigned long long)__float_as_uint(s) << 32)
                | (unsigned long long)(0xFFFFFFFFu - (unsigned)p);
            if (key > best) best = key;
        }
        #pragma unroll
        for (int off = 16; off; off >>= 1) {
            unsigned long long o = __shfl_down_sync(0xffffffffu, best, off);
            if (o > best) best = o;
        }
        if (lane == 0) s_k[wid] = best;
        __syncthreads();
        if (tid == 0) {
            unsigned long long b = s_k[0];
            #pragma unroll
            for (int w = 1; w < 8; w++) if (s_k[w] > b) b = s_k[w];
            s_top = (int)(0xFFFFFFFFu - (unsigned)(b & 0xFFFFFFFFu));
        }
        __syncthreads();
    }
    const int top = s_top;
    const int ty  = top / FT, tx = top % FT;

    // ---- D: hp_offset head at the winner (weights from smem)
    if (tid < C) {
        float acc = s_odb[tid];
        #pragma unroll
        for (int r = 0; r < 3; r++) {
            int gi = ty + r - 1;
            if (gi < 0 || gi >= FT) continue;
            #pragma unroll
            for (int s = 0; s < 3; s++) {
                int gj = tx + s - 1;
                if (gj < 0 || gj >= FT) continue;
                float xv = __ldg(&x[(tid * FT + gi) * FT + gj]) * XNORM_A - 1.0f;
                acc += s_odw[tid * 9 + r * 3 + s] * xv;
            }
        }
        s_y[tid] = acc;
    }
    __syncthreads();
    if (tid < HC) {
        float a = s_ob1[tid];
        #pragma unroll
        for (int kk = 0; kk < C; kk++) a += s_ow1[tid * C + kk] * s_y[kk];
        s_z[tid] = fmaxf(a, 0.f);
    }
    __syncthreads();
    if (wid < 2) {
        float a = s_ow2[wid * HC + lane]      * s_z[lane]
                + s_ow2[wid * HC + lane + 32] * s_z[lane + 32]
                + s_ow2[wid * HC + lane + 64] * s_z[lane + 64];
        #pragma unroll
        for (int off = 16; off; off >>= 1)
            a += __shfl_down_sync(0xffffffffu, a, off);
        if (lane == 0) {
            float base = wid ? (float)tx : (float)ty;
            out[k * 3 + wid] = (a + s_ob2[wid] + base) * OUT_SCALE;
        }
    }
    if (tid == 64)
        out[k * 3 + 2] = hmap[top];   // stored sigmoid
}

// ---------------------------------------------------------------------------
extern "C" void kernel_launch(void* const* d_in, const int* in_sizes, int n_in,
                              void* d_out, int out_size)
{
    const float* x = (const float*)d_in[0];

    heads_kernel<<<NBLK, HT>>>(
        x,
        (const float*)d_in[1],  (const float*)d_in[2],
        (const float*)d_in[3],  (const float*)d_in[4],
        (const float*)d_in[5],  (const float*)d_in[6],
        (const float*)d_in[7],  (const float*)d_in[8],
        (const float*)d_in[9],  (const float*)d_in[10],
        (const float*)d_in[11], (const float*)d_in[12]);

    cudaLaunchConfig_t cfg = {};
    cfg.gridDim  = dim3(17);
    cfg.blockDim = dim3(256);
    cfg.dynamicSmemBytes = 0;
    cfg.stream = (cudaStream_t)0;
    cudaLaunchAttribute attr[1];
    attr[0].id = cudaLaunchAttributeProgrammaticStreamSerialization;
    attr[0].val.programmaticStreamSerializationAllowed = 1;
    cfg.attrs = attr;
    cfg.numAttrs = 1;

    cudaLaunchKernelEx(&cfg, decode_kernel,
        x,
        (const float*)d_in[13], (const float*)d_in[14],
        (const float*)d_in[15], (const float*)d_in[16],
        (const float*)d_in[17], (const float*)d_in[18],
        (const float*)d_in[19], (const float*)d_in[20],
        (const float*)d_in[21], (const float*)d_in[22],
        (const float*)d_in[23], (const float*)d_in[24],
        (float*)d_out);
}

// round 15
// speedup vs baseline: 1.2407x; 1.0014x over previous
#include <cuda_runtime.h>
#include <cuda_bf16.h>
#include <math.h>

#define C    24
#define HC   96
#define FT   48
#define NPOS (FT*FT)
#define P    16           // positions per block (144 blocks = 1 wave)
#define NBLK (NPOS / P)   // 144
#define HT   384          // heads kernel block size
#define SUBS 8            // decode blocks per keypoint (8*288 = 2304)
#define SPAN 288          // positions per decode block
#define XNORM_A 0.007843137718737125f
#define DELTA 1.8f
#define OUT_SCALE 0.02083333395421505f

// Dense hm_hp SIGMOIDS, channel-major [ch][pos]
__device__ float g_hmhp[17 * NPOS];
// Per-block center argmax keys: (score_bits<<32) | (0xFFFFFFFF - pos)
__device__ unsigned long long g_part[NBLK];
// Per-keypoint argmax accumulators + arrival counters (self-resetting)
__device__ unsigned long long g_ckey[17];
__device__ int g_cnt[17];

__device__ __forceinline__ float fast_sig(float v) {
    return __fdividef(1.0f, 1.0f + __expf(-v));
}

// ---------------------------------------------------------------------------
// Kernel 1 (primary): dense hm_hp (sigmoid) + hm heads + per-block center key.
// 144 blocks x 384 threads (R14, proven).
// ---------------------------------------------------------------------------
__global__ __launch_bounds__(HT) void heads_kernel(
    const float* __restrict__ x,
    const float* __restrict__ w_dw0, const float* __restrict__ b_dw0,
    const float* __restrict__ w1_0,  const float* __restrict__ b1_0,
    const float* __restrict__ w2_0,  const float* __restrict__ b2_0,
    const float* __restrict__ w_dw1, const float* __restrict__ b_dw1,
    const float* __restrict__ w1_1,  const float* __restrict__ b1_1,
    const float* __restrict__ w2_1,  const float* __restrict__ b2_1)
{
    __shared__ float xs[C][3][P + 2];
    __shared__ float ys[2][P][28];
    __shared__ float zs[2][P][100];
    __shared__ unsigned long long skey[P];

    const int tid   = threadIdx.x;
    const int pbase = blockIdx.x * P;
    const int row   = pbase / FT;
    const int col0  = pbase % FT;

    for (int idx = tid; idx < C * 3 * (P + 2); idx += HT) {
        int c  = idx / (3 * (P + 2));
        int r  = (idx / (P + 2)) % 3;
        int cc = idx % (P + 2);
        int gi = row + r - 1;
        int gj = col0 + cc - 1;
        float v = 0.f;
        if (gi >= 0 && gi < FT && gj >= 0 && gj < FT)
            v = x[(c * FT + gi) * FT + gj] * XNORM_A - 1.0f;
        xs[c][r][cc] = v;
    }
    __syncthreads();

    for (int idx = tid; idx < 2 * C * P; idx += HT) {
        int h   = idx / (C * P);
        int rem = idx % (C * P);
        int c   = rem / P;
        int p   = rem % P;
        const float* wd = h ? w_dw1 : w_dw0;
        const float* bd = h ? b_dw1 : b_dw0;
        float acc = bd[c];
        #pragma unroll
        for (int r = 0; r < 3; r++)
            #pragma unroll
            for (int s = 0; s < 3; s++)
                acc += wd[c * 9 + r * 3 + s] * xs[c][r][p + s];
        ys[h][p][c] = acc;
    }
    __syncthreads();

    // pw1 split into two 8-position halves: 384 tasks, 1 per thread
    {
        int h    = tid / (HC * 2);
        int rem  = tid % (HC * 2);
        int oc   = rem >> 1;
        int half = rem & 1;
        int p0   = half * 8;
        const float* w1 = h ? w1_1 : w1_0;
        const float* b1 = h ? b1_1 : b1_0;
        float acc[8];
        float b = b1[oc];
        #pragma unroll
        for (int p = 0; p < 8; p++) acc[p] = b;
        #pragma unroll
        for (int k = 0; k < C; k++) {
            float wv = __ldg(&w1[oc * C + k]);
            #pragma unroll
            for (int p = 0; p < 8; p++) acc[p] += wv * ys[h][p0 + p][k];
        }
        #pragma unroll
        for (int p = 0; p < 8; p++) zs[h][p0 + p][oc] = fmaxf(acc[p], 0.f);
    }
    __syncthreads();

    if (tid < 18 * P) {
        int combo = tid / P;
        int p     = tid % P;
        int pos   = pbase + p;
        if (combo < 17) {
            int oc = combo;
            float acc = b2_0[oc];
            #pragma unroll 8
            for (int k = 0; k < HC; k++)
                acc += __ldg(&w2_0[oc * HC + k]) * zs[0][p][k];
            g_hmhp[oc * NPOS + pos] = fast_sig(acc);
        } else {
            float acc = b2_1[0];
            #pragma unroll 8
            for (int k = 0; k < HC; k++)
                acc += __ldg(&w2_1[k]) * zs[1][p][k];
            float sig = fast_sig(acc);
            float gy = (float)row - (FT * 0.5f);
            float gx = (float)(col0 + p) - (FT * 0.5f);
            float s = __fdividef(sig, sqrtf(gy * gy + gx * gx) + DELTA);
            skey[p] = ((unsigned long long)__float_as_uint(s) << 32)
                    | (unsigned long long)(0xFFFFFFFFu - (unsigned)pos);
        }
    }
    __syncthreads();
    if (tid == 0) {
        unsigned long long best = skey[0];
        #pragma unroll
        for (int p = 1; p < P; p++) if (skey[p] > best) best = skey[p];
        g_part[blockIdx.x] = best;
    }

    cudaTriggerProgrammaticLaunchCompletion();
}

// ---------------------------------------------------------------------------
// Kernel 2 (dependent, PDL): decode, 17*8 = 136 blocks x 256 threads.
// Preamble: stage weights. Post-sync: prefetch slice -> A -> B -> C ->
// atomicMax; the 8th arriving block per keypoint runs D + output.
// ---------------------------------------------------------------------------
__global__ __launch_bounds__(256) void decode_kernel(
    const float* __restrict__ x,
    const float* __restrict__ hps_dw_w, const float* __restrict__ hps_dw_b,
    const float* __restrict__ hps_w1,   const float* __restrict__ hps_b1,
    const float* __restrict__ hps_w2,   const float* __restrict__ hps_b2,
    const float* __restrict__ off_dw_w, const float* __restrict__ off_dw_b,
    const float* __restrict__ off_w1,   const float* __restrict__ off_b1,
    const float* __restrict__ off_w2,   const float* __restrict__ off_b2,
    float* __restrict__ out)
{
    __shared__ float s_hw1[HC * C];
    __shared__ float s_ow1[HC * C];
    __shared__ float s_hdw[C * 9], s_odw[C * 9];
    __shared__ float s_hdb[C],     s_odb[C];
    __shared__ float s_hb1[HC],    s_ob1[HC];
    __shared__ float s_hw2[2 * HC], s_ow2[2 * HC];
    __shared__ float s_hb2[2],      s_ob2[2];
    __shared__ unsigned long long s_k[8];
    __shared__ int   s_ct, s_top, s_fin;
    __shared__ float s_y[C];
    __shared__ float s_z[HC];
    __shared__ float s_kc[2];

    const int k    = blockIdx.x >> 3;    // keypoint 0..16
    const int sub  = blockIdx.x & 7;     // slice 0..7
    const int tid  = threadIdx.x;
    const int lane = tid & 31;
    const int wid  = tid >> 5;

    // ---- preamble: weight staging, independent of the primary kernel
    for (int i = tid; i < HC * C; i += 256) {
        s_hw1[i] = __ldg(&hps_w1[i]);
        s_ow1[i] = __ldg(&off_w1[i]);
    }
    for (int i = tid; i < C * 9; i += 256) {
        s_hdw[i] = __ldg(&hps_dw_w[i]);
        s_odw[i] = __ldg(&off_dw_w[i]);
    }
    if (tid < C)  { s_hdb[tid] = __ldg(&hps_dw_b[tid]); s_odb[tid] = __ldg(&off_dw_b[tid]); }
    if (tid < HC) { s_hb1[tid] = __ldg(&hps_b1[tid]);   s_ob1[tid] = __ldg(&off_b1[tid]); }
    for (int i = tid; i < 2 * HC; i += 256) {
        s_hw2[i] = __ldg(&hps_w2[2 * k * HC + i]);
        s_ow2[i] = __ldg(&off_w2[2 * k * HC + i]);
    }
    if (tid < 2) { s_hb2[tid] = __ldg(&hps_b2[2 * k + tid]); s_ob2[tid] = __ldg(&off_b2[2 * k + tid]); }

    // ---- wait for the primary grid's results
    cudaGridDependencySynchronize();

    // ---- prefetch this block's 288-position slice (overlaps A and B)
    const float* hmap = g_hmhp + k * NPOS;
    const int p0 = sub * SPAN + tid;
    const int p1 = sub * SPAN + 256 + tid;          // only tid<32 valid
    float pre0 = __ldg(&hmap[p0]);
    float pre1 = (tid < 32) ? __ldg(&hmap[p1]) : 0.f;

    // ---- A: reduce 144 per-block center keys (warp 0)
    if (wid == 0) {
        unsigned long long key = 0ULL;
        for (int i = lane; i < NBLK; i += 32) {
            unsigned long long v = g_part[i];
            if (v > key) key = v;
        }
        #pragma unroll
        for (int off = 16; off; off >>= 1) {
            unsigned long long o = __shfl_down_sync(0xffffffffu, key, off);
            if (o > key) key = o;
        }
        if (lane == 0)
            s_ct = (int)(0xFFFFFFFFu - (unsigned)(key & 0xFFFFFFFFu));
    }
    __syncthreads();   // also orders preamble smem staging
    const int ct  = s_ct;
    const int cty = ct / FT, ctx = ct % FT;

    // ---- B: hps head at the center (weights from smem, block-parallel)
    if (tid < C) {
        float acc = s_hdb[tid];
        #pragma unroll
        for (int r = 0; r < 3; r++) {
            int gi = cty + r - 1;
            if (gi < 0 || gi >= FT) continue;
            #pragma unroll
            for (int s = 0; s < 3; s++) {
                int gj = ctx + s - 1;
                if (gj < 0 || gj >= FT) continue;
                float xv = __ldg(&x[(tid * FT + gi) * FT + gj]) * XNORM_A - 1.0f;
                acc += s_hdw[tid * 9 + r * 3 + s] * xv;
            }
        }
        s_y[tid] = acc;
    }
    __syncthreads();
    if (tid < HC) {
        float a = s_hb1[tid];
        #pragma unroll
        for (int kk = 0; kk < C; kk++) a += s_hw1[tid * C + kk] * s_y[kk];
        s_z[tid] = fmaxf(a, 0.f);
    }
    __syncthreads();
    if (wid < 2) {
        float a = s_hw2[wid * HC + lane]      * s_z[lane]
                + s_hw2[wid * HC + lane + 32] * s_z[lane + 32]
                + s_hw2[wid * HC + lane + 64] * s_z[lane + 64];
        #pragma unroll
        for (int off = 16; off; off >>= 1)
            a += __shfl_down_sync(0xffffffffu, a, off);
        if (lane == 0)
            s_kc[wid] = a + s_hb2[wid] + (wid ? (float)ctx : (float)cty);
    }
    __syncthreads();

    // ---- C: score this block's slice (1-2 positions/thread, prefetched)
    const float ky = s_kc[0];
    const float kx = s_kc[1];
    {
        unsigned long long best;
        {
            int py = p0 / FT;
            float dy = (float)py - ky;
            float dx = (float)(p0 - py * FT) - kx;
            float s = __fdividef(pre0, sqrtf(dy * dy + dx * dx) + DELTA);
            best = ((unsigned long long)__float_as_uint(s) << 32)
                 | (unsigned long long)(0xFFFFFFFFu - (unsigned)p0);
        }
        if (tid < 32) {
            int py = p1 / FT;
            float dy = (float)py - ky;
            float dx = (float)(p1 - py * FT) - kx;
            float s = __fdividef(pre1, sqrtf(dy * dy + dx * dx) + DELTA);
            unsigned long long key2 =
                ((unsigned long long)__float_as_uint(s) << 32)
                | (unsigned long long)(0xFFFFFFFFu - (unsigned)p1);
            if (key2 > best) best = key2;
        }
        #pragma unroll
        for (int off = 16; off; off >>= 1) {
            unsigned long long o = __shfl_down_sync(0xffffffffu, best, off);
            if (o > best) best = o;
        }
        if (lane == 0) s_k[wid] = best;
        __syncthreads();
        if (tid == 0) {
            unsigned long long b = s_k[0];
            #pragma unroll
            for (int w = 1; w < 8; w++) if (s_k[w] > b) b = s_k[w];
            atomicMax(&g_ckey[k], b);
            __threadfence();
            int n = atomicAdd(&g_cnt[k], 1);
            if (n == SUBS - 1) {
                unsigned long long fin = atomicExch(&g_ckey[k], 0ULL); // read+reset
                atomicExch(&g_cnt[k], 0);
                s_top = (int)(0xFFFFFFFFu - (unsigned)(fin & 0xFFFFFFFFu));
                s_fin = 1;
            } else {
                s_fin = 0;
            }
        }
        __syncthreads();
    }
    if (!s_fin) return;

    const int top = s_top;
    const int ty  = top / FT, tx = top % FT;

    // ---- D: hp_offset head at the winner (weights from smem) + outputs
    if (tid < C) {
        float acc = s_odb[tid];
        #pragma unroll
        for (int r = 0; r < 3; r++) {
            int gi = ty + r - 1;
            if (gi < 0 || gi >= FT) continue;
            #pragma unroll
            for (int s = 0; s < 3; s++) {
                int gj = tx + s - 1;
                if (gj < 0 || gj >= FT) continue;
                float xv = __ldg(&x[(tid * FT + gi) * FT + gj]) * XNORM_A - 1.0f;
                acc += s_odw[tid * 9 + r * 3 + s] * xv;
            }
        }
        s_y[tid] = acc;
    }
    __syncthreads();
    if (tid < HC) {
        float a = s_ob1[tid];
        #pragma unroll
        for (int kk = 0; kk < C; kk++) a += s_ow1[tid * C + kk] * s_y[kk];
        s_z[tid] = fmaxf(a, 0.f);
    }
    __syncthreads();
    if (wid < 2) {
        float a = s_ow2[wid * HC + lane]      * s_z[lane]
                + s_ow2[wid * HC + lane + 32] * s_z[lane + 32]
                + s_ow2[wid * HC + lane + 64] * s_z[lane + 64];
        #pragma unroll
        for (int off = 16; off; off >>= 1)
            a += __shfl_down_sync(0xffffffffu, a, off);
        if (lane == 0) {
            float base = wid ? (float)tx : (float)ty;
            out[k * 3 + wid] = (a + s_ob2[wid] + base) * OUT_SCALE;
        }
    }
    if (tid == 64)
        out[k * 3 + 2] = __ldg(&hmap[top]);   // stored sigmoid
}

// ---------------------------------------------------------------------------
extern "C" void kernel_launch(void* const* d_in, const int* in_sizes, int n_in,
                              void* d_out, int out_size)
{
    const float* x = (const float*)d_in[0];

    heads_kernel<<<NBLK, HT>>>(
        x,
        (const float*)d_in[1],  (const float*)d_in[2],
        (const float*)d_in[3],  (const float*)d_in[4],
        (const float*)d_in[5],  (const float*)d_in[6],
        (const float*)d_in[7],  (const float*)d_in[8],
        (const float*)d_in[9],  (const float*)d_in[10],
        (const float*)d_in[11], (const float*)d_in[12]);

    cudaLaunchConfig_t cfg = {};
    cfg.gridDim  = dim3(17 * SUBS);
    cfg.blockDim = dim3(256);
    cfg.dynamicSmemBytes = 0;
    cfg.stream = (cudaStream_t)0;
    cudaLaunchAttribute attr[1];
    attr[0].id = cudaLaunchAttributeProgrammaticStreamSerialization;
    attr[0].val.programmaticStreamSerializationAllowed = 1;
    cfg.attrs = attr;
    cfg.numAttrs = 1;

    cudaLaunchKernelEx(&cfg, decode_kernel,
        x,
        (const float*)d_in[13], (const float*)d_in[14],
        (const float*)d_in[15], (const float*)d_in[16],
        (const float*)d_in[17], (const float*)d_in[18],
        (const float*)d_in[19], (const float*)d_in[20],
        (const float*)d_in[21], (const float*)d_in[22],
        (const float*)d_in[23], (const float*)d_in[24],
        (float*)d_out);
}

// round 17
// speedup vs baseline: 1.3750x; 1.1082x over previous
#include <cuda_runtime.h>
#include <cuda_bf16.h>
#include <math.h>

#define C    24
#define HC   96
#define FT   48
#define NPOS (FT*FT)
#define P    16           // positions per block (144 blocks = 1 wave)
#define NBLK (NPOS / P)   // 144
#define HT   384          // heads kernel block size
#define XNORM_A 0.007843137718737125f
#define DELTA 1.8f
#define OUT_SCALE 0.02083333395421505f

// Dense hm_hp SIGMOIDS, channel-major [ch][pos]
__device__ float g_hmhp[17 * NPOS];
// Per-block center argmax keys: (score_bits<<32) | (0xFFFFFFFF - pos)
__device__ unsigned long long g_part[NBLK];

__device__ __forceinline__ float fast_sig(float v) {
    return __fdividef(1.0f, 1.0f + __expf(-v));
}

// ---------------------------------------------------------------------------
// Kernel 1 (primary): dense hm_hp (sigmoid) + hm heads + per-block center key.
// 144 blocks x 384 threads (R14, proven).
// ---------------------------------------------------------------------------
__global__ __launch_bounds__(HT) void heads_kernel(
    const float* __restrict__ x,
    const float* __restrict__ w_dw0, const float* __restrict__ b_dw0,
    const float* __restrict__ w1_0,  const float* __restrict__ b1_0,
    const float* __restrict__ w2_0,  const float* __restrict__ b2_0,
    const float* __restrict__ w_dw1, const float* __restrict__ b_dw1,
    const float* __restrict__ w1_1,  const float* __restrict__ b1_1,
    const float* __restrict__ w2_1,  const float* __restrict__ b2_1)
{
    __shared__ float xs[C][3][P + 2];
    __shared__ float ys[2][P][28];
    __shared__ float zs[2][P][100];
    __shared__ unsigned long long skey[P];

    const int tid   = threadIdx.x;
    const int pbase = blockIdx.x * P;
    const int row   = pbase / FT;
    const int col0  = pbase % FT;

    for (int idx = tid; idx < C * 3 * (P + 2); idx += HT) {
        int c  = idx / (3 * (P + 2));
        int r  = (idx / (P + 2)) % 3;
        int cc = idx % (P + 2);
        int gi = row + r - 1;
        int gj = col0 + cc - 1;
        float v = 0.f;
        if (gi >= 0 && gi < FT && gj >= 0 && gj < FT)
            v = x[(c * FT + gi) * FT + gj] * XNORM_A - 1.0f;
        xs[c][r][cc] = v;
    }
    __syncthreads();

    for (int idx = tid; idx < 2 * C * P; idx += HT) {
        int h   = idx / (C * P);
        int rem = idx % (C * P);
        int c   = rem / P;
        int p   = rem % P;
        const float* wd = h ? w_dw1 : w_dw0;
        const float* bd = h ? b_dw1 : b_dw0;
        float acc = bd[c];
        #pragma unroll
        for (int r = 0; r < 3; r++)
            #pragma unroll
            for (int s = 0; s < 3; s++)
                acc += wd[c * 9 + r * 3 + s] * xs[c][r][p + s];
        ys[h][p][c] = acc;
    }
    __syncthreads();

    // pw1 split into two 8-position halves: 384 tasks, 1 per thread
    {
        int h    = tid / (HC * 2);
        int rem  = tid % (HC * 2);
        int oc   = rem >> 1;
        int half = rem & 1;
        int p0   = half * 8;
        const float* w1 = h ? w1_1 : w1_0;
        const float* b1 = h ? b1_1 : b1_0;
        float acc[8];
        float b = b1[oc];
        #pragma unroll
        for (int p = 0; p < 8; p++) acc[p] = b;
        #pragma unroll
        for (int k = 0; k < C; k++) {
            float wv = __ldg(&w1[oc * C + k]);
            #pragma unroll
            for (int p = 0; p < 8; p++) acc[p] += wv * ys[h][p0 + p][k];
        }
        #pragma unroll
        for (int p = 0; p < 8; p++) zs[h][p0 + p][oc] = fmaxf(acc[p], 0.f);
    }
    __syncthreads();

    if (tid < 18 * P) {
        int combo = tid / P;
        int p     = tid % P;
        int pos   = pbase + p;
        if (combo < 17) {
            int oc = combo;
            float acc = b2_0[oc];
            #pragma unroll 8
            for (int k = 0; k < HC; k++)
                acc += __ldg(&w2_0[oc * HC + k]) * zs[0][p][k];
            g_hmhp[oc * NPOS + pos] = fast_sig(acc);
        } else {
            float acc = b2_1[0];
            #pragma unroll 8
            for (int k = 0; k < HC; k++)
                acc += __ldg(&w2_1[k]) * zs[1][p][k];
            float sig = fast_sig(acc);
            float gy = (float)row - (FT * 0.5f);
            float gx = (float)(col0 + p) - (FT * 0.5f);
            float s = __fdividef(sig, sqrtf(gy * gy + gx * gx) + DELTA);
            skey[p] = ((unsigned long long)__float_as_uint(s) << 32)
                    | (unsigned long long)(0xFFFFFFFFu - (unsigned)pos);
        }
    }
    __syncthreads();
    if (tid == 0) {
        unsigned long long best = skey[0];
        #pragma unroll
        for (int p = 1; p < P; p++) if (skey[p] > best) best = skey[p];
        g_part[blockIdx.x] = best;
    }

    cudaTriggerProgrammaticLaunchCompletion();
}

// ---------------------------------------------------------------------------
// One-warp head evaluation at position (py, px): depthwise 3x3 -> pw1 -> the
// two pw2 channels (2k, 2k+1). Weights in smem (w1 TRANSPOSED: [kk*96+oc]).
// Returns (r0, r1) on lane 0.
// ---------------------------------------------------------------------------
__device__ __forceinline__ void warp_head2(
    const float* __restrict__ x,
    const float* s_dw, const float* s_db,
    const float* s_w1t, const float* s_b1,
    const float* s_w2, const float* s_b2,     // s_w2: rows 2k,2k+1 packed [2*HC]
    int py, int px, int lane,
    float& r0, float& r1)
{
    // depthwise: lane c < 24 computes channel c
    float y = 0.f;
    if (lane < C) {
        y = s_db[lane];
        #pragma unroll
        for (int r = 0; r < 3; r++) {
            int gi = py + r - 1;
            if (gi < 0 || gi >= FT) continue;
            #pragma unroll
            for (int s = 0; s < 3; s++) {
                int gj = px + s - 1;
                if (gj < 0 || gj >= FT) continue;
                float xv = __ldg(&x[(lane * FT + gi) * FT + gj]) * XNORM_A - 1.0f;
                y += s_dw[lane * 9 + r * 3 + s] * xv;
            }
        }
    }
    // pw1: lane handles rows lane, lane+32, lane+64; y exchanged via shfl
    float z0 = s_b1[lane], z1 = s_b1[lane + 32], z2 = s_b1[lane + 64];
    #pragma unroll
    for (int kk = 0; kk < C; kk++) {
        float yk = __shfl_sync(0xffffffffu, y, kk);
        z0 += s_w1t[kk * HC + lane]      * yk;
        z1 += s_w1t[kk * HC + lane + 32] * yk;
        z2 += s_w1t[kk * HC + lane + 64] * yk;
    }
    z0 = fmaxf(z0, 0.f); z1 = fmaxf(z1, 0.f); z2 = fmaxf(z2, 0.f);
    // pw2: two channels, each lane contributes 3 products
    float a0 = z0 * s_w2[lane]      + z1 * s_w2[lane + 32]      + z2 * s_w2[lane + 64];
    float a1 = z0 * s_w2[HC + lane] + z1 * s_w2[HC + lane + 32] + z2 * s_w2[HC + lane + 64];
    #pragma unroll
    for (int off = 16; off; off >>= 1) {
        a0 += __shfl_down_sync(0xffffffffu, a0, off);
        a1 += __shfl_down_sync(0xffffffffu, a1, off);
    }
    r0 = a0 + s_b2[0];
    r1 = a1 + s_b2[1];
}

// ---------------------------------------------------------------------------
// Kernel 2 (dependent, PDL): decode, 17 blocks x 256 threads, THREE block syncs.
// ---------------------------------------------------------------------------
__global__ __launch_bounds__(256) void decode_kernel(
    const float* __restrict__ x,
    const float* __restrict__ hps_dw_w, const float* __restrict__ hps_dw_b,
    const float* __restrict__ hps_w1,   const float* __restrict__ hps_b1,
    const float* __restrict__ hps_w2,   const float* __restrict__ hps_b2,
    const float* __restrict__ off_dw_w, const float* __restrict__ off_dw_b,
    const float* __restrict__ off_w1,   const float* __restrict__ off_b1,
    const float* __restrict__ off_w2,   const float* __restrict__ off_b2,
    float* __restrict__ out)
{
    __shared__ float s_hw1t[C * HC];     // transposed: [kk*96+oc]
    __shared__ float s_ow1t[C * HC];
    __shared__ float s_hdw[C * 9], s_odw[C * 9];
    __shared__ float s_hdb[C],     s_odb[C];
    __shared__ float s_hb1[HC],    s_ob1[HC];
    __shared__ float s_hw2[2 * HC], s_ow2[2 * HC];
    __shared__ float s_hb2[2],      s_ob2[2];
    __shared__ unsigned long long s_k[8];
    __shared__ float s_kc[2];

    const int k    = blockIdx.x;
    const int tid  = threadIdx.x;
    const int lane = tid & 31;
    const int wid  = tid >> 5;

    // ---- preamble: weight staging (w1 transposed), independent of primary
    for (int i = tid; i < HC * C; i += 256) {
        int oc = i / C, kk = i % C;
        s_hw1t[kk * HC + oc] = __ldg(&hps_w1[i]);
        s_ow1t[kk * HC + oc] = __ldg(&off_w1[i]);
    }
    for (int i = tid; i < C * 9; i += 256) {
        s_hdw[i] = __ldg(&hps_dw_w[i]);
        s_odw[i] = __ldg(&off_dw_w[i]);
    }
    for (int i = tid; i < 2 * HC; i += 256) {        // full coverage (bugfix)
        s_hw2[i] = __ldg(&hps_w2[2 * k * HC + i]);
        s_ow2[i] = __ldg(&off_w2[2 * k * HC + i]);
    }
    if (tid < C)  { s_hdb[tid] = __ldg(&hps_dw_b[tid]); s_odb[tid] = __ldg(&off_dw_b[tid]); }
    if (tid < HC) { s_hb1[tid] = __ldg(&hps_b1[tid]);   s_ob1[tid] = __ldg(&off_b1[tid]); }
    if (tid < 2) { s_hb2[tid] = __ldg(&hps_b2[2 * k + tid]); s_ob2[tid] = __ldg(&off_b2[2 * k + tid]); }

    // ---- wait for the primary grid's results
    cudaGridDependencySynchronize();

    // ---- prefetch this keypoint's heatmap slice into registers
    const float* hmap = g_hmhp + k * NPOS;
    float pre[NPOS / 256];
    #pragma unroll
    for (int i = 0; i < NPOS / 256; i++)
        pre[i] = __ldg(&hmap[tid + i * 256]);

    __syncthreads();                                   // sync #0: staging -> use

    // ---- warp 0 alone: phase A then phase B, fully warp-local
    if (wid == 0) {
        // A: reduce 144 center keys
        unsigned long long key = 0ULL;
        #pragma unroll
        for (int i = 0; i < 5; i++) {
            int idx = lane + i * 32;
            if (idx < NBLK) {
                unsigned long long v = g_part[idx];
                if (v > key) key = v;
            }
        }
        #pragma unroll
        for (int off = 16; off; off >>= 1) {
            unsigned long long o = __shfl_down_sync(0xffffffffu, key, off);
            if (o > key) key = o;
        }
        key = __shfl_sync(0xffffffffu, key, 0);
        const int ct  = (int)(0xFFFFFFFFu - (unsigned)(key & 0xFFFFFFFFu));
        const int cty = ct / FT, ctx = ct % FT;

        // B: hps head at the center, warp-local
        float r0, r1;
        warp_head2(x, s_hdw, s_hdb, s_hw1t, s_hb1, s_hw2, s_hb2,
                   cty, ctx, lane, r0, r1);
        if (lane == 0) {
            s_kc[0] = r0 + (float)cty;
            s_kc[1] = r1 + (float)ctx;
        }
    }
    __syncthreads();                                   // sync #1

    // ---- C: all 8 warps score their prefetched positions
    {
        const float ky = s_kc[0];
        const float kx = s_kc[1];
        unsigned long long best = 0ULL;
        #pragma unroll
        for (int i = 0; i < NPOS / 256; i++) {
            int p = tid + i * 256;
            int py = p / FT;
            float dy = (float)py - ky;
            float dx = (float)(p - py * FT) - kx;
            float s = __fdividef(pre[i], sqrtf(dy * dy + dx * dx) + DELTA);
            unsigned long long kk2 =
                ((unsigned long long)__float_as_uint(s) << 32)
                | (unsigned long long)(0xFFFFFFFFu - (unsigned)p);
            if (kk2 > best) best = kk2;
        }
        #pragma unroll
        for (int off = 16; off; off >>= 1) {
            unsigned long long o = __shfl_down_sync(0xffffffffu, best, off);
            if (o > best) best = o;
        }
        if (lane == 0) s_k[wid] = best;
    }
    __syncthreads();                                   // sync #2

    // ---- warp 0 alone: final reduce + phase D + outputs
    if (wid == 0) {
        unsigned long long b = (lane < 8) ? s_k[lane] : 0ULL;
        #pragma unroll
        for (int off = 4; off; off >>= 1) {
            unsigned long long o = __shfl_down_sync(0xffffffffu, b, off);
            if (o > b) b = o;
        }
        b = __shfl_sync(0xffffffffu, b, 0);
        const int top = (int)(0xFFFFFFFFu - (unsigned)(b & 0xFFFFFFFFu));
        const int ty  = top / FT, tx = top % FT;

        // issue the confidence load early; latency hides under D
        float conf = 0.f;
        if (lane == 0) conf = __ldg(&hmap[top]);

        float r0, r1;
        warp_head2(x, s_odw, s_odb, s_ow1t, s_ob1, s_ow2, s_ob2,
                   ty, tx, lane, r0, r1);
        if (lane == 0) {
            out[k * 3 + 0] = (r0 + (float)ty) * OUT_SCALE;
            out[k * 3 + 1] = (r1 + (float)tx) * OUT_SCALE;
            out[k * 3 + 2] = conf;
        }
    }
}

// ---------------------------------------------------------------------------
extern "C" void kernel_launch(void* const* d_in, const int* in_sizes, int n_in,
                              void* d_out, int out_size)
{
    const float* x = (const float*)d_in[0];

    heads_kernel<<<NBLK, HT>>>(
        x,
        (const float*)d_in[1],  (const float*)d_in[2],
        (const float*)d_in[3],  (const float*)d_in[4],
        (const float*)d_in[5],  (const float*)d_in[6],
        (const float*)d_in[7],  (const float*)d_in[8],
        (const float*)d_in[9],  (const float*)d_in[10],
        (const float*)d_in[11], (const float*)d_in[12]);

    cudaLaunchConfig_t cfg = {};
    cfg.gridDim  = dim3(17);
    cfg.blockDim = dim3(256);
    cfg.dynamicSmemBytes = 0;
    cfg.stream = (cudaStream_t)0;
    cudaLaunchAttribute attr[1];
    attr[0].id = cudaLaunchAttributeProgrammaticStreamSerialization;
    attr[0].val.programmaticStreamSerializationAllowed = 1;
    cfg.attrs = attr;
    cfg.numAttrs = 1;

    cudaLaunchKernelEx(&cfg, decode_kernel,
        x,
        (const float*)d_in[13], (const float*)d_in[14],
        (const float*)d_in[15], (const float*)d_in[16],
        (const float*)d_in[17], (const float*)d_in[18],
        (const float*)d_in[19], (const float*)d_in[20],
        (const float*)d_in[21], (const float*)d_in[22],
        (const float*)d_in[23], (const float*)d_in[24],
        (float*)d_out);
}